// round 10
// baseline (speedup 1.0000x reference)
#include <cuda_runtime.h>
#include <math.h>
#include <stdint.h>

#define BB 32
#define CC 256
#define HWD 96
#define ROW4 (HWD/4)         // 24 float4 per row
#define PLANE (HWD*HWD)      // 9216
#define PLANE_BYTES (PLANE*4)
#define NPLANES (BB*CC)      // 8192
#define KK 9
#define W2ROWS (CC*KK)       // 2304
#define NT 288               // 24 strips x 12 row-chunks

// scratch — monotonic counters; epoch derived from ticket => replay-safe
__device__ float        g_pooled[NPLANES];
__device__ float        g_wdyn[NPLANES * KK];
__device__ unsigned int g_cnt[BB];    // pool arrivals  (monotonic)
__device__ unsigned int g_flag[BB];   // dyn completions (monotonic)

struct Row6 { float4 c; float l, r; };

__device__ __forceinline__ Row6 load_row_s(const float* __restrict__ s,
                                           int y, int xb, int x4) {
    Row6 o;
    const float* rp = s + y * HWD;
    o.c = *reinterpret_cast<const float4*>(rp + xb);
    o.l = (x4 == 0)        ? o.c.y : rp[xb - 1];      // reflect col -1 -> 1
    o.r = (x4 == ROW4 - 1) ? o.c.z : rp[xb + 4];      // reflect col 96 -> 94
    return o;
}

__device__ __forceinline__ void row_fma(float4& acc, const Row6& rr,
                                        float wl, float wc, float wr) {
    acc.x += rr.l   * wl + rr.c.x * wc + rr.c.y * wr;
    acc.y += rr.c.x * wl + rr.c.y * wc + rr.c.z * wr;
    acc.z += rr.c.y * wl + rr.c.z * wc + rr.c.w * wr;
    acc.w += rr.c.z * wl + rr.c.w * wc + rr.r   * wr;
}

__global__ __launch_bounds__(NT, 2) void fused_kernel(
    const float* __restrict__ x,
    const float* __restrict__ w1,
    const float* __restrict__ b1,
    const float* __restrict__ w2,
    const float* __restrict__ b2,
    float* __restrict__ out)
{
    const int plane = blockIdx.x;          // in-order: batches complete in order
    const int b     = plane >> 8;
    const int tid   = threadIdx.x;

    __shared__ __align__(16) float s[PLANE];   // the plane, read ONCE from DRAM
    __shared__ float ps[CC];
    __shared__ float hs[CC];
    __shared__ float ws[16];
    __shared__ unsigned int s_old;
    __shared__ __align__(8) uint64_t mbar;

    uint32_t s_u32, mbar_u32;
    asm("{ .reg .u64 t; cvta.to.shared.u64 t, %1; cvt.u32.u64 %0, t; }"
        : "=r"(s_u32) : "l"((const void*)s));
    asm("{ .reg .u64 t; cvta.to.shared.u64 t, %1; cvt.u32.u64 %0, t; }"
        : "=r"(mbar_u32) : "l"((const void*)&mbar));

    // ---------------- TMA load plane -> smem --------------------------------
    if (tid == 0) {
        asm volatile("mbarrier.init.shared.b64 [%0], 1;" :: "r"(mbar_u32) : "memory");
        asm volatile("fence.proxy.async.shared::cta;" ::: "memory");
        asm volatile("mbarrier.arrive.expect_tx.shared.b64 _, [%0], %1;"
                     :: "r"(mbar_u32), "r"((unsigned)PLANE_BYTES) : "memory");
        asm volatile(
            "cp.async.bulk.shared::cta.global.mbarrier::complete_tx::bytes "
            "[%0], [%1], %2, [%3];"
            :: "r"(s_u32), "l"(x + (size_t)plane * PLANE),
               "r"((unsigned)PLANE_BYTES), "r"(mbar_u32)
            : "memory");
    }
    __syncthreads();   // mbar.init visible before anyone waits
    {
        unsigned done = 0;
        while (!done) {
            asm volatile(
                "{\n .reg .pred p;\n"
                " mbarrier.try_wait.parity.acquire.cta.shared::cta.b64 p, [%1], %2, 0x989680;\n"
                " selp.b32 %0, 1, 0, p;\n}"
                : "=r"(done) : "r"(mbar_u32), "r"(0u) : "memory");
        }
    }

    // ---------------- pool from smem ---------------------------------------
    {
        const float4* sp4 = reinterpret_cast<const float4*>(s);
        float sum = 0.f;
#pragma unroll
        for (int it = 0; it < 8; ++it) {           // 2304/288 = 8
            float4 v = sp4[tid + it * NT];
            sum += (v.x + v.y) + (v.z + v.w);
        }
#pragma unroll
        for (int o = 16; o > 0; o >>= 1)
            sum += __shfl_xor_sync(0xffffffffu, sum, o);
        const int lane = tid & 31, wid = tid >> 5;
        if (lane == 0) ws[wid] = sum;
        __syncthreads();
        if (tid == 0) {
            float t = 0.f;
#pragma unroll
            for (int i = 0; i < 9; ++i) t += ws[i];
            g_pooled[plane] = t * (1.0f / (float)PLANE);
            __threadfence();                        // release pooled value
            s_old = atomicAdd(&g_cnt[b], 1u);       // ticket
        }
        __syncthreads();
    }
    const unsigned int old   = s_old;
    const unsigned int epoch = old >> 8;            // launch index for batch b
    const bool is_last = ((old & 255u) == 255u);    // uniform across block

    // ---------------- dyn (last arriver) or single wait ---------------------
    if (is_last) {
        __threadfence();                            // acquire all pooled[b]
        if (tid < CC) ps[tid] = g_pooled[b * CC + tid];
        __syncthreads();
        if (tid < CC) {
            float acc = b1[tid];
            const float4* __restrict__ wr =
                reinterpret_cast<const float4*>(w1 + (size_t)tid * CC);
            const float4* __restrict__ pv = reinterpret_cast<const float4*>(ps);
#pragma unroll 8
            for (int k = 0; k < CC / 4; ++k) {
                float4 a = pv[k]; float4 w = wr[k];
                acc += a.x * w.x + a.y * w.y + a.z * w.z + a.w * w.w;
            }
            hs[tid] = 0.5f * acc * (1.0f + erff(acc * 0.70710678118654752f));
        }
        __syncthreads();
        if (tid < CC) {
            const float4* __restrict__ hv = reinterpret_cast<const float4*>(hs);
#pragma unroll
            for (int r0 = 0; r0 < KK; ++r0) {
                const int r = r0 * 256 + tid;
                float acc = b2[r];
                const float4* __restrict__ wr =
                    reinterpret_cast<const float4*>(w2 + (size_t)r * CC);
#pragma unroll 8
                for (int k = 0; k < CC / 4; ++k) {
                    float4 a = hv[k]; float4 w = wr[k];
                    acc += a.x * w.x + a.y * w.y + a.z * w.z + a.w * w.w;
                }
                g_wdyn[(size_t)b * W2ROWS + r] = acc;
            }
        }
        __syncthreads();
        if (tid == 0) {
            __threadfence();                        // release wdyn
            atomicAdd(&g_flag[b], 1u);
        }
    } else {
        if (tid == 0) {
            while (*(volatile unsigned int*)&g_flag[b] <= epoch)
                __nanosleep(128);
            __threadfence();                        // acquire wdyn
        }
    }
    __syncthreads();

    // ---------------- conv from smem (register window) ----------------------
    float w[KK];
    const float* __restrict__ wd = g_wdyn + (size_t)plane * KK;
#pragma unroll
    for (int i = 0; i < KK; ++i) w[i] = wd[i];

    const int x4 = tid % ROW4;      // strip 0..23
    const int cy = tid / ROW4;      // chunk 0..11
    const int y0 = cy * 8;
    const int xb = x4 * 4;

    Row6 prev = load_row_s(s, (cy == 0) ? 1 : (y0 - 1), xb, x4);  // reflect -1 -> 1
    Row6 cur  = load_row_s(s, y0, xb, x4);

    float4 res[8];
#pragma unroll
    for (int i = 0; i < 8; ++i) {
        const int y  = y0 + i;
        const int yn = (y == HWD - 1) ? HWD - 2 : y + 1;          // reflect 96 -> 94
        Row6 nxt = load_row_s(s, yn, xb, x4);
        float4 acc = make_float4(0.f, 0.f, 0.f, 0.f);
        row_fma(acc, prev, w[0], w[1], w[2]);
        row_fma(acc, cur,  w[3], w[4], w[5]);
        row_fma(acc, nxt,  w[6], w[7], w[8]);
        res[i] = acc;
        prev = cur; cur = nxt;
    }

    __syncthreads();   // everyone done READING s
#pragma unroll
    for (int i = 0; i < 8; ++i)
        *reinterpret_cast<float4*>(s + (y0 + i) * HWD + xb) = res[i];
    __syncthreads();   // everyone done WRITING s

    if (tid == 0) {
        asm volatile("fence.proxy.async.shared::cta;" ::: "memory");
        asm volatile(
            "cp.async.bulk.global.shared::cta.bulk_group [%0], [%1], %2;"
            :: "l"(out + (size_t)plane * PLANE), "r"(s_u32),
               "r"((unsigned)PLANE_BYTES)
            : "memory");
        asm volatile("cp.async.bulk.commit_group;" ::: "memory");
        asm volatile("cp.async.bulk.wait_group.read 0;" ::: "memory");
    }
}

// ---------------------------------------------------------------------------
extern "C" void kernel_launch(void* const* d_in, const int* in_sizes, int n_in,
                              void* d_out, int out_size) {
    const float* x  = (const float*)d_in[0];   // (32,256,96,96)
    const float* w1 = (const float*)d_in[1];   // (256,256)
    const float* b1 = (const float*)d_in[2];   // (256,)
    const float* w2 = (const float*)d_in[3];   // (2304,256)
    const float* b2 = (const float*)d_in[4];   // (2304,)
    float* out = (float*)d_out;

    fused_kernel<<<NPLANES, NT>>>(x, w1, b1, w2, b2, out);
}

// round 11
// speedup vs baseline: 9.1808x; 9.1808x over previous
#include <cuda_runtime.h>
#include <math.h>
#include <stdint.h>

#define BB 32
#define CC 256
#define HWD 96
#define ROW4 (HWD/4)         // 24 float4 per row
#define PLANE (HWD*HWD)      // 9216
#define PLANE_BYTES (PLANE*4)
#define NPLANES (BB*CC)      // 8192
#define KK 9
#define W2ROWS (CC*KK)       // 2304
#define CHUNK_B 4            // batches per chunk: 37.7 MB (L2-resident)
#define NCHUNK (BB/CHUNK_B)  // 8
#define CPL (CHUNK_B*CC)     // 1024 planes per chunk
#define NT 288               // 24 strips x 12 row-chunks

// scratch (no allocations allowed)
__device__ float g_pooled[NPLANES];
__device__ float g_wdyn[NPLANES * KK];

// ---------------------------------------------------------------------------
struct Row6 { float4 c; float l, r; };

__device__ __forceinline__ Row6 load_row_s(const float* __restrict__ s,
                                           int y, int xb, int x4) {
    Row6 o;
    const float* rp = s + y * HWD;
    o.c = *reinterpret_cast<const float4*>(rp + xb);
    o.l = (x4 == 0)        ? o.c.y : rp[xb - 1];      // reflect col -1 -> 1
    o.r = (x4 == ROW4 - 1) ? o.c.z : rp[xb + 4];      // reflect col 96 -> 94
    return o;
}

__device__ __forceinline__ void row_fma(float4& acc, const Row6& rr,
                                        float wl, float wc, float wr) {
    acc.x += rr.l   * wl + rr.c.x * wc + rr.c.y * wr;
    acc.y += rr.c.x * wl + rr.c.y * wc + rr.c.z * wr;
    acc.z += rr.c.y * wl + rr.c.z * wc + rr.c.w * wr;
    acc.w += rr.c.z * wl + rr.c.w * wc + rr.r   * wr;
}

// ---------------------------------------------------------------------------
// mix kernel: even blocks = conv of chunk conv_p0 (reads hit L2, warmed by the
// pool half of the PREVIOUS launch); odd blocks = pool of chunk pool_p0
// (default-cached LDG -> warms L2 for the NEXT launch's conv half).
// conv_p0 / pool_p0 are plane bases; -1 disables that half.
// ---------------------------------------------------------------------------
__global__ __launch_bounds__(NT) void mix_kernel(const float* __restrict__ x,
                                                 float* __restrict__ out,
                                                 int conv_p0, int pool_p0) {
    const int tid = threadIdx.x;
    int type, idx;
    if (conv_p0 >= 0 && pool_p0 >= 0) { type = blockIdx.x & 1; idx = blockIdx.x >> 1; }
    else if (conv_p0 >= 0)            { type = 0;              idx = blockIdx.x; }
    else                              { type = 1;              idx = blockIdx.x; }

    __shared__ __align__(16) float s[PLANE];
    __shared__ __align__(8) uint64_t mbar;
    __shared__ float ws[16];

    if (type == 1) {
        // ---------------- pool block (plain LDG, warms L2) ------------------
        const int plane = pool_p0 + idx;
        const float4* __restrict__ xp =
            reinterpret_cast<const float4*>(x + (size_t)plane * PLANE);
        float sum = 0.f;
#pragma unroll
        for (int it = 0; it < 8; ++it) {            // 2304/288 = 8
            float4 v = xp[tid + it * NT];
            sum += (v.x + v.y) + (v.z + v.w);
        }
#pragma unroll
        for (int o = 16; o > 0; o >>= 1)
            sum += __shfl_xor_sync(0xffffffffu, sum, o);
        const int lane = tid & 31, wid = tid >> 5;
        if (lane == 0) ws[wid] = sum;
        __syncthreads();
        if (tid == 0) {
            float t = 0.f;
#pragma unroll
            for (int i = 0; i < 9; ++i) t += ws[i];
            g_pooled[plane] = t * (1.0f / (float)PLANE);
        }
        return;
    }

    // ---------------- conv block (TMA load; reads should be L2 hits) --------
    const int plane = conv_p0 + idx;

    uint32_t s_u32, mbar_u32;
    asm("{ .reg .u64 t; cvta.to.shared.u64 t, %1; cvt.u32.u64 %0, t; }"
        : "=r"(s_u32) : "l"((const void*)s));
    asm("{ .reg .u64 t; cvta.to.shared.u64 t, %1; cvt.u32.u64 %0, t; }"
        : "=r"(mbar_u32) : "l"((const void*)&mbar));

    if (tid == 0) {
        asm volatile("mbarrier.init.shared.b64 [%0], 1;" :: "r"(mbar_u32) : "memory");
        asm volatile("fence.proxy.async.shared::cta;" ::: "memory");
        asm volatile("mbarrier.arrive.expect_tx.shared.b64 _, [%0], %1;"
                     :: "r"(mbar_u32), "r"((unsigned)PLANE_BYTES) : "memory");
        asm volatile(
            "cp.async.bulk.shared::cta.global.mbarrier::complete_tx::bytes "
            "[%0], [%1], %2, [%3];"
            :: "r"(s_u32), "l"(x + (size_t)plane * PLANE),
               "r"((unsigned)PLANE_BYTES), "r"(mbar_u32)
            : "memory");
    }

    // fetch the 9 dynamic weights while the bulk copy flies
    float w[KK];
    const float* __restrict__ wd = g_wdyn + (size_t)plane * KK;
#pragma unroll
    for (int i = 0; i < KK; ++i) w[i] = wd[i];

    __syncthreads();   // mbar.init visible before anyone waits
    {
        unsigned done = 0;
        while (!done) {
            asm volatile(
                "{\n .reg .pred p;\n"
                " mbarrier.try_wait.parity.acquire.cta.shared::cta.b64 p, [%1], %2, 0x989680;\n"
                " selp.b32 %0, 1, 0, p;\n}"
                : "=r"(done) : "r"(mbar_u32), "r"(0u) : "memory");
        }
    }

    const int x4 = tid % ROW4;      // strip 0..23
    const int cy = tid / ROW4;      // chunk 0..11
    const int y0 = cy * 8;
    const int xb = x4 * 4;

    Row6 prev = load_row_s(s, (cy == 0) ? 1 : (y0 - 1), xb, x4);  // reflect -1 -> 1
    Row6 cur  = load_row_s(s, y0, xb, x4);

    float4* __restrict__ o4 =
        reinterpret_cast<float4*>(out + (size_t)plane * PLANE);

#pragma unroll
    for (int i = 0; i < 8; ++i) {
        const int y  = y0 + i;
        const int yn = (y == HWD - 1) ? HWD - 2 : y + 1;          // reflect 96 -> 94
        Row6 nxt = load_row_s(s, yn, xb, x4);
        float4 acc = make_float4(0.f, 0.f, 0.f, 0.f);
        row_fma(acc, prev, w[0], w[1], w[2]);
        row_fma(acc, cur,  w[3], w[4], w[5]);
        row_fma(acc, nxt,  w[6], w[7], w[8]);
        __stcs(&o4[y * ROW4 + x4], acc);                          // evict-first
        prev = cur; cur = nxt;
    }
}

// ---------------------------------------------------------------------------
// dyn kernel, chunked. grid = (9, CHUNK_B).
// ---------------------------------------------------------------------------
__global__ __launch_bounds__(256) void dyn_kernel(const float* __restrict__ w1,
                                                  const float* __restrict__ b1,
                                                  const float* __restrict__ w2,
                                                  const float* __restrict__ b2,
                                                  int b0) {
    const int b  = b0 + blockIdx.y;
    const int r0 = blockIdx.x;
    const int c  = threadIdx.x;
    __shared__ float ps[CC];
    __shared__ float hs[CC];
    ps[c] = g_pooled[b * CC + c];
    __syncthreads();

    {
        float acc = b1[c];
        const float4* __restrict__ wr =
            reinterpret_cast<const float4*>(w1 + (size_t)c * CC);
        const float4* __restrict__ pv = reinterpret_cast<const float4*>(ps);
#pragma unroll 8
        for (int k = 0; k < CC / 4; ++k) {
            float4 a = pv[k]; float4 w = wr[k];
            acc += a.x * w.x + a.y * w.y + a.z * w.z + a.w * w.w;
        }
        hs[c] = 0.5f * acc * (1.0f + erff(acc * 0.70710678118654752f));
    }
    __syncthreads();

    const int r = r0 * 256 + c;
    float acc = b2[r];
    const float4* __restrict__ wr =
        reinterpret_cast<const float4*>(w2 + (size_t)r * CC);
    const float4* __restrict__ hv = reinterpret_cast<const float4*>(hs);
#pragma unroll 8
    for (int k = 0; k < CC / 4; ++k) {
        float4 a = hv[k]; float4 w = wr[k];
        acc += a.x * w.x + a.y * w.y + a.z * w.z + a.w * w.w;
    }
    g_wdyn[(size_t)b * W2ROWS + r] = acc;
}

// ---------------------------------------------------------------------------
extern "C" void kernel_launch(void* const* d_in, const int* in_sizes, int n_in,
                              void* d_out, int out_size) {
    const float* x  = (const float*)d_in[0];   // (32,256,96,96)
    const float* w1 = (const float*)d_in[1];   // (256,256)
    const float* b1 = (const float*)d_in[2];   // (256,)
    const float* w2 = (const float*)d_in[3];   // (2304,256)
    const float* b2 = (const float*)d_in[4];   // (2304,)
    float* out = (float*)d_out;

    // prologue: pool chunk 0
    mix_kernel<<<CPL, NT>>>(x, out, -1, 0);
    dyn_kernel<<<dim3(KK, CHUNK_B), 256>>>(w1, b1, w2, b2, 0);
    // steady state: conv(c) overlapped with pool(c+1) in one launch
    for (int c = 0; c < NCHUNK - 1; ++c) {
        mix_kernel<<<2 * CPL, NT>>>(x, out, c * CPL, (c + 1) * CPL);
        dyn_kernel<<<dim3(KK, CHUNK_B), 256>>>(w1, b1, w2, b2, (c + 1) * CHUNK_B);
    }
    // epilogue: conv last chunk
    mix_kernel<<<CPL, NT>>>(x, out, (NCHUNK - 1) * CPL, -1);
}